// round 5
// baseline (speedup 1.0000x reference)
#include <cuda_runtime.h>

// 16 lanes cooperate per point. Lane layout g = lane & 15:
//   dz = g>>3, dy = (g>>2)&1, sub = g&3; dx = sub>>1, feat-half = sub&1.
// Each lane loads 16B of the 64B chunk [corner(dx=0) 32B | corner(dx=1) 32B].

// HINT: 0 = plain ld.global.nc, 1/2 = ld.global.nc with L2 cache_hint policy
template<int HINT>
__device__ __forceinline__ float4 ld_cb(const float4* __restrict__ p, unsigned long long pol)
{
    float4 v;
    if (HINT != 0) {
        asm volatile("ld.global.nc.L2::cache_hint.v4.f32 {%0,%1,%2,%3}, [%4], %5;"
                     : "=f"(v.x), "=f"(v.y), "=f"(v.z), "=f"(v.w)
                     : "l"(p), "l"(pol));
    } else {
        v = __ldg(p);
    }
    return v;
}

template<int RES, int HINT>
__device__ __forceinline__ void lerp_add(const float* __restrict__ cb,
                                         float px, float py, float pz,
                                         float sx, float cx,
                                         float sy, float cy,
                                         float sz, float cz,
                                         int dy, int dz, int sub,
                                         unsigned long long pol,
                                         float4& acc)
{
    const float s = (float)(RES - 1);
    float x = px * s, y = py * s, z = pz * s;

    // pts in [0,1) -> x,y,z >= 0 -> trunc == floor; clamp upper bound in int
    int x0 = min((int)x, RES - 2);
    int y0 = min((int)y, RES - 2);
    int z0 = min((int)z, RES - 2);

    // d ? f : 1-f  ==  fma(s, f, c) with s=+/-1, c=0/1 (hoisted per lane)
    float wx = fmaf(sx, x - (float)x0, cx);
    float wy = fmaf(sy, y - (float)y0, cy);
    float wz = fmaf(sz, z - (float)z0, cz);
    float w  = wx * wy * wz;

    int idx = x0 + (y0 + dy) * RES + (z0 + dz) * (RES * RES);
    const float4* p = reinterpret_cast<const float4*>(cb) + ((size_t)idx * 2 + sub);
    float4 v = ld_cb<HINT>(p, pol);

    acc.x = fmaf(w, v.x, acc.x);
    acc.y = fmaf(w, v.y, acc.y);
    acc.z = fmaf(w, v.z, acc.z);
    acc.w = fmaf(w, v.w, acc.w);
}

__global__ void __launch_bounds__(256) dense_grid_coop_kernel(
    const float* __restrict__ pts,
    const float* __restrict__ cb0,
    const float* __restrict__ cb1,
    const float* __restrict__ cb2,
    const float* __restrict__ cb3,
    const float* __restrict__ cb4,
    float* __restrict__ out,
    int n)
{
    int tid  = blockIdx.x * blockDim.x + threadIdx.x;
    int lane = threadIdx.x & 31;
    int g    = lane & 15;
    int pt   = (tid >> 5) * 2 + (lane >> 4);

    bool valid = (pt < n);
    int ptc = valid ? pt : (n - 1);

    float px = pts[3 * ptc + 0];
    float py = pts[3 * ptc + 1];
    float pz = pts[3 * ptc + 2];

    int sub = g & 3;
    int dx  = sub >> 1;
    int dy  = (g >> 2) & 1;
    int dz  = g >> 3;

    float sx = dx ? 1.0f : -1.0f, cx = dx ? 0.0f : 1.0f;
    float sy = dy ? 1.0f : -1.0f, cy = dy ? 0.0f : 1.0f;
    float sz = dz ? 1.0f : -1.0f, cz = dz ? 0.0f : 1.0f;

    // L2 policies: pin cb3 (reused 64MB table), stream cb4 (512MB, no reuse)
    unsigned long long pol_pin, pol_stream;
    asm("createpolicy.fractional.L2::evict_last.b64 %0, 1.0;"  : "=l"(pol_pin));
    asm("createpolicy.fractional.L2::evict_first.b64 %0, 1.0;" : "=l"(pol_stream));

    float4 acc = make_float4(0.f, 0.f, 0.f, 0.f);

    lerp_add< 16, 0>(cb0, px, py, pz, sx, cx, sy, cy, sz, cz, dy, dz, sub, 0ull,       acc);
    lerp_add< 32, 0>(cb1, px, py, pz, sx, cx, sy, cy, sz, cz, dy, dz, sub, 0ull,       acc);
    lerp_add< 64, 0>(cb2, px, py, pz, sx, cx, sy, cy, sz, cz, dy, dz, sub, 0ull,       acc);
    lerp_add<128, 1>(cb3, px, py, pz, sx, cx, sy, cy, sz, cz, dy, dz, sub, pol_pin,    acc);
    lerp_add<256, 2>(cb4, px, py, pz, sx, cx, sy, cy, sz, cz, dy, dz, sub, pol_stream, acc);

    // reduce 8 partials per feature-half: xor over g bits 1,2,3
    #pragma unroll
    for (int off = 2; off <= 8; off <<= 1) {
        acc.x += __shfl_xor_sync(0xffffffffu, acc.x, off);
        acc.y += __shfl_xor_sync(0xffffffffu, acc.y, off);
        acc.z += __shfl_xor_sync(0xffffffffu, acc.z, off);
        acc.w += __shfl_xor_sync(0xffffffffu, acc.w, off);
    }

    if (valid && g < 2) {
        float4* o = reinterpret_cast<float4*>(out + (size_t)pt * 8) + g;
        *o = acc;
    }
}

extern "C" void kernel_launch(void* const* d_in, const int* in_sizes, int n_in,
                              void* d_out, int out_size)
{
    const float* pts = (const float*)d_in[0];
    const float* cb0 = (const float*)d_in[1];
    const float* cb1 = (const float*)d_in[2];
    const float* cb2 = (const float*)d_in[3];
    const float* cb3 = (const float*)d_in[4];
    const float* cb4 = (const float*)d_in[5];
    float* out = (float*)d_out;

    int n = in_sizes[0] / 3;                 // pts is [N,3]
    int total_threads = ((n + 1) / 2) * 32;  // 16 lanes/pt, 2 pts/warp
    int threads = 256;
    int blocks = (total_threads + threads - 1) / threads;
    dense_grid_coop_kernel<<<blocks, threads>>>(pts, cb0, cb1, cb2, cb3, cb4, out, n);
}

// round 6
// speedup vs baseline: 1.0483x; 1.0483x over previous
#include <cuda_runtime.h>

// 8 lanes cooperate per point; lane g = lane&7 owns corner (dx,dy,dz)=(g&1,(g>>1)&1,g>>2).
// Each lane loads its corner's full 32B feature row with one 256-bit load.
// 4 points per warp. Butterfly reduce-and-distribute leaves feat g in lane g.

// HINT: 0 = plain nc, 1 = L2::evict_last (cb3), 2 = L2::evict_first (cb4)
template<int HINT>
__device__ __forceinline__ void ld_corner256(const float* __restrict__ p, float* v)
{
    unsigned r0, r1, r2, r3, r4, r5, r6, r7;
    if (HINT == 1) {
        asm("ld.global.nc.L2::evict_last.v8.b32 {%0,%1,%2,%3,%4,%5,%6,%7}, [%8];"
            : "=r"(r0), "=r"(r1), "=r"(r2), "=r"(r3),
              "=r"(r4), "=r"(r5), "=r"(r6), "=r"(r7) : "l"(p));
    } else if (HINT == 2) {
        asm("ld.global.nc.L2::evict_first.v8.b32 {%0,%1,%2,%3,%4,%5,%6,%7}, [%8];"
            : "=r"(r0), "=r"(r1), "=r"(r2), "=r"(r3),
              "=r"(r4), "=r"(r5), "=r"(r6), "=r"(r7) : "l"(p));
    } else {
        asm("ld.global.nc.v8.b32 {%0,%1,%2,%3,%4,%5,%6,%7}, [%8];"
            : "=r"(r0), "=r"(r1), "=r"(r2), "=r"(r3),
              "=r"(r4), "=r"(r5), "=r"(r6), "=r"(r7) : "l"(p));
    }
    v[0] = __uint_as_float(r0); v[1] = __uint_as_float(r1);
    v[2] = __uint_as_float(r2); v[3] = __uint_as_float(r3);
    v[4] = __uint_as_float(r4); v[5] = __uint_as_float(r5);
    v[6] = __uint_as_float(r6); v[7] = __uint_as_float(r7);
}

template<int RES, int HINT>
__device__ __forceinline__ void lerp_add(const float* __restrict__ cb,
                                         float px, float py, float pz,
                                         int dx, int dy, int dz,
                                         float sx, float cx,
                                         float sy, float cy,
                                         float sz, float cz,
                                         float* acc)
{
    const float s = (float)(RES - 1);
    float x = px * s, y = py * s, z = pz * s;

    // pts in [0,1) -> coords >= 0 -> trunc == floor; clamp upper in int
    int x0 = min((int)x, RES - 2);
    int y0 = min((int)y, RES - 2);
    int z0 = min((int)z, RES - 2);

    // d ? f : 1-f == fma(s, f, c), s=+/-1, c=0/1 (hoisted per lane)
    float wx = fmaf(sx, x - (float)x0, cx);
    float wy = fmaf(sy, y - (float)y0, cy);
    float wz = fmaf(sz, z - (float)z0, cz);
    float w  = wx * wy * wz;

    int idx = (x0 + dx) + (y0 + dy) * RES + (z0 + dz) * (RES * RES);
    const float* p = cb + (size_t)idx * 8;

    float v[8];
    ld_corner256<HINT>(p, v);

    #pragma unroll
    for (int i = 0; i < 8; ++i)
        acc[i] = fmaf(w, v[i], acc[i]);
}

__global__ void __launch_bounds__(256) dense_grid_8lane_kernel(
    const float* __restrict__ pts,
    const float* __restrict__ cb0,
    const float* __restrict__ cb1,
    const float* __restrict__ cb2,
    const float* __restrict__ cb3,
    const float* __restrict__ cb4,
    float* __restrict__ out,
    int n)
{
    int tid  = blockIdx.x * blockDim.x + threadIdx.x;
    int lane = threadIdx.x & 31;
    int g    = lane & 7;                      // corner id within 8-lane group
    int pt   = (tid >> 5) * 4 + (lane >> 3);  // 4 points per warp

    bool valid = (pt < n);
    int ptc = valid ? pt : (n - 1);

    float px = __ldg(&pts[3 * ptc + 0]);
    float py = __ldg(&pts[3 * ptc + 1]);
    float pz = __ldg(&pts[3 * ptc + 2]);

    int dx = g & 1, dy = (g >> 1) & 1, dz = g >> 2;

    float sx = dx ? 1.0f : -1.0f, cx = dx ? 0.0f : 1.0f;
    float sy = dy ? 1.0f : -1.0f, cy = dy ? 0.0f : 1.0f;
    float sz = dz ? 1.0f : -1.0f, cz = dz ? 0.0f : 1.0f;

    float acc[8];
    #pragma unroll
    for (int i = 0; i < 8; ++i) acc[i] = 0.0f;

    lerp_add< 16, 0>(cb0, px, py, pz, dx, dy, dz, sx, cx, sy, cy, sz, cz, acc);
    lerp_add< 32, 0>(cb1, px, py, pz, dx, dy, dz, sx, cx, sy, cy, sz, cz, acc);
    lerp_add< 64, 0>(cb2, px, py, pz, dx, dy, dz, sx, cx, sy, cy, sz, cz, acc);
    lerp_add<128, 1>(cb3, px, py, pz, dx, dy, dz, sx, cx, sy, cy, sz, cz, acc);  // evict_last
    lerp_add<256, 2>(cb4, px, py, pz, dx, dy, dz, sx, cx, sy, cy, sz, cz, acc);  // evict_first

    // Butterfly reduce-and-distribute over the 8-lane group:
    // after round b (offset 2^b), lane keeps feats whose bit b equals bit b of g.
    // End state: lane g holds the full sum for feature g.
    float t[4];
    {
        bool k = (g & 1);
        #pragma unroll
        for (int j = 0; j < 4; ++j) {
            float snd = k ? acc[2 * j] : acc[2 * j + 1];
            float rcv = __shfl_xor_sync(0xffffffffu, snd, 1);
            float kep = k ? acc[2 * j + 1] : acc[2 * j];
            t[j] = kep + rcv;
        }
    }
    float u[2];
    {
        bool k = (g >> 1) & 1;
        #pragma unroll
        for (int j = 0; j < 2; ++j) {
            float snd = k ? t[2 * j] : t[2 * j + 1];
            float rcv = __shfl_xor_sync(0xffffffffu, snd, 2);
            float kep = k ? t[2 * j + 1] : t[2 * j];
            u[j] = kep + rcv;
        }
    }
    float r;
    {
        bool k = (g >> 2) & 1;
        float snd = k ? u[0] : u[1];
        float rcv = __shfl_xor_sync(0xffffffffu, snd, 4);
        float kep = k ? u[1] : u[0];
        r = kep + rcv;
    }

    if (valid)
        out[(size_t)pt * 8 + g] = r;   // warp writes 128B contiguous
}

extern "C" void kernel_launch(void* const* d_in, const int* in_sizes, int n_in,
                              void* d_out, int out_size)
{
    const float* pts = (const float*)d_in[0];
    const float* cb0 = (const float*)d_in[1];
    const float* cb1 = (const float*)d_in[2];
    const float* cb2 = (const float*)d_in[3];
    const float* cb3 = (const float*)d_in[4];
    const float* cb4 = (const float*)d_in[5];
    float* out = (float*)d_out;

    int n = in_sizes[0] / 3;                 // pts is [N,3]
    int total_threads = ((n + 3) / 4) * 32;  // 8 lanes/pt, 4 pts/warp
    int threads = 256;
    int blocks = (total_threads + threads - 1) / threads;
    dense_grid_8lane_kernel<<<blocks, threads>>>(pts, cb0, cb1, cb2, cb3, cb4, out, n);
}